// round 1
// baseline (speedup 1.0000x reference)
#include <cuda_runtime.h>

#define BB 64
#define TT 2048
#define DD 512

// Scratch (allocation-free contract: __device__ globals)
__device__ float g_phis[BB * DD];
__device__ float g_v[BB * DD];
__device__ float g_e[BB * TT];
__device__ float g_hsum[BB * TT];

// ---------------------------------------------------------------------------
// Kernel 1: phi_s[b,a] = dot(s[b,:], phi_w[a,:]) + phi_b[a]
// One warp per 'a'; phi_w row pinned in registers, loop over all 64 b.
// phi_w read exactly once from DRAM (1 MB); s stays L1/L2-hot.
// ---------------------------------------------------------------------------
__global__ void k_phis(const float* __restrict__ s,
                       const float* __restrict__ phi_w,
                       const float* __restrict__ phi_b) {
    const int warp = threadIdx.x >> 5;
    const int lane = threadIdx.x & 31;
    const int a = blockIdx.x * 8 + warp;   // grid 64 x block 256 -> 512 a's

    const float4* w4 = (const float4*)(phi_w + (size_t)a * DD);
    float4 w[4];
    #pragma unroll
    for (int j = 0; j < 4; j++) w[j] = w4[lane + 32 * j];
    const float bias = phi_b[a];

    for (int b = 0; b < BB; b++) {
        const float4* s4 = (const float4*)(s + (size_t)b * DD);
        float acc = 0.f;
        #pragma unroll
        for (int j = 0; j < 4; j++) {
            float4 sv = s4[lane + 32 * j];
            acc += w[j].x * sv.x + w[j].y * sv.y + w[j].z * sv.z + w[j].w * sv.w;
        }
        #pragma unroll
        for (int off = 16; off; off >>= 1)
            acc += __shfl_xor_sync(0xffffffffu, acc, off);
        if (lane == 0) g_phis[b * DD + a] = acc + bias;
    }
}

// ---------------------------------------------------------------------------
// Kernel 2: v[b,k] = sum_a phi_s[b,a] * psi_w[a,k]
// One block per b, thread per k; psi_w stream fully coalesced (L2-served
// after first pass). 4 accumulators for ILP.
// NOTE: psi_b is intentionally dropped — it only adds a per-b constant to
// the scores, which softmax is invariant to.
// ---------------------------------------------------------------------------
__global__ void k_v(const float* __restrict__ psi_w) {
    const int b = blockIdx.x;
    const int k = threadIdx.x;   // 512 threads
    __shared__ float ph[DD];
    ph[k] = g_phis[b * DD + k];
    __syncthreads();

    float a0 = 0.f, a1 = 0.f, a2 = 0.f, a3 = 0.f;
    #pragma unroll 8
    for (int a = 0; a < DD; a += 4) {
        a0 += ph[a + 0] * psi_w[(size_t)(a + 0) * DD + k];
        a1 += ph[a + 1] * psi_w[(size_t)(a + 1) * DD + k];
        a2 += ph[a + 2] * psi_w[(size_t)(a + 2) * DD + k];
        a3 += ph[a + 3] * psi_w[(size_t)(a + 3) * DD + k];
    }
    g_v[b * DD + k] = (a0 + a1) + (a2 + a3);
}

// ---------------------------------------------------------------------------
// Kernel 3 (the DRAM-bound pass): one warp per (b,t) row of h.
// Single streaming read of h (268 MB) computes BOTH e[b,t] = v[b].h[b,t]
// and hsum[b,t] = sum_k h[b,t,k]. v[b] is L2/L1-hot (128 KB total).
// ---------------------------------------------------------------------------
__global__ void k_scores(const float* __restrict__ h) {
    const int row  = blockIdx.x * (blockDim.x >> 5) + (threadIdx.x >> 5);
    const int lane = threadIdx.x & 31;
    const int b = row >> 11;   // row / 2048

    const float4* h4 = (const float4*)(h + (size_t)row * DD);
    const float4* v4 = (const float4*)(g_v + (size_t)b * DD);

    float e = 0.f, hs = 0.f;
    #pragma unroll
    for (int j = 0; j < 4; j++) {
        float4 hv = h4[lane + 32 * j];
        float4 vv = v4[lane + 32 * j];
        e  += hv.x * vv.x + hv.y * vv.y + hv.z * vv.z + hv.w * vv.w;
        hs += (hv.x + hv.y) + (hv.z + hv.w);
    }
    #pragma unroll
    for (int off = 16; off; off >>= 1) {
        e  += __shfl_xor_sync(0xffffffffu, e,  off);
        hs += __shfl_xor_sync(0xffffffffu, hs, off);
    }
    if (lane == 0) { g_e[row] = e; g_hsum[row] = hs; }
}

// ---------------------------------------------------------------------------
// Kernel 4: per-b softmax over T=2048 and output c = alpha * hsum.
// One block (256 threads) per b; 8 elements per thread; block max/sum reduce.
// ---------------------------------------------------------------------------
__global__ void k_softmax(float* __restrict__ out) {
    const int b = blockIdx.x;
    const int tid = threadIdx.x;             // 256 threads
    const int lane = tid & 31, wid = tid >> 5;
    __shared__ float red[8];

    float er[8];
    #pragma unroll
    for (int i = 0; i < 8; i++) er[i] = g_e[b * TT + tid + i * 256];

    float m = er[0];
    #pragma unroll
    for (int i = 1; i < 8; i++) m = fmaxf(m, er[i]);
    #pragma unroll
    for (int off = 16; off; off >>= 1)
        m = fmaxf(m, __shfl_xor_sync(0xffffffffu, m, off));
    if (lane == 0) red[wid] = m;
    __syncthreads();
    float M = red[0];
    #pragma unroll
    for (int w = 1; w < 8; w++) M = fmaxf(M, red[w]);
    __syncthreads();

    float ex[8];
    float sum = 0.f;
    #pragma unroll
    for (int i = 0; i < 8; i++) { ex[i] = expf(er[i] - M); sum += ex[i]; }
    #pragma unroll
    for (int off = 16; off; off >>= 1)
        sum += __shfl_xor_sync(0xffffffffu, sum, off);
    if (lane == 0) red[wid] = sum;
    __syncthreads();
    float S = red[0];
    #pragma unroll
    for (int w = 1; w < 8; w++) S += red[w];
    const float inv = 1.f / S;

    #pragma unroll
    for (int i = 0; i < 8; i++) {
        int idx = b * TT + tid + i * 256;
        out[idx] = ex[i] * inv * g_hsum[idx];
    }
}

// ---------------------------------------------------------------------------
extern "C" void kernel_launch(void* const* d_in, const int* in_sizes, int n_in,
                              void* d_out, int out_size) {
    const float* s     = (const float*)d_in[0];   // [64, 512]
    const float* h     = (const float*)d_in[1];   // [64, 2048, 512]
    const float* phi_w = (const float*)d_in[2];   // [512, 512]
    const float* phi_b = (const float*)d_in[3];   // [512]
    const float* psi_w = (const float*)d_in[4];   // [512, 512]
    // d_in[5] = psi_b: provably unused (softmax shift invariance)
    float* out = (float*)d_out;                   // [64, 2048] fp32

    k_phis<<<64, 256>>>(s, phi_w, phi_b);
    k_v<<<64, 512>>>(psi_w);
    k_scores<<<(BB * TT) / 8, 256>>>(h);
    k_softmax<<<64, 256>>>(out);
}

// round 3
// speedup vs baseline: 1.3053x; 1.3053x over previous
#include <cuda_runtime.h>

#define BB 64
#define TT 2048
#define DD 512

// Scratch (allocation-free contract: __device__ globals)
__device__ float g_v[BB * DD];
__device__ float g_e[BB * TT];
__device__ float g_hsum[BB * TT];

// ---------------------------------------------------------------------------
// k_prep: fused  phi_s[b,:] = s[b] @ phi_w^T + phi_b   (warp dots)
//                v[b,:]     = phi_s[b,:] @ psi_w       (float4 columns)
// One block per b (64 blocks x 512 threads). psi_b dropped: it only shifts
// e[b,:] by a per-b constant, and softmax is shift-invariant.
// ---------------------------------------------------------------------------
__global__ void k_prep(const float* __restrict__ s,
                       const float* __restrict__ phi_w,
                       const float* __restrict__ phi_b,
                       const float* __restrict__ psi_w) {
    const int b    = blockIdx.x;
    const int tid  = threadIdx.x;          // 512
    const int lane = tid & 31;
    const int warp = tid >> 5;             // 16 warps

    __shared__ float  sh_s[DD];
    __shared__ float  sh_ph[DD];
    __shared__ float4 sh_vp[4][DD / 4];

    sh_s[tid] = s[(size_t)b * DD + tid];
    __syncthreads();
    const float4* s4 = (const float4*)sh_s;

    // Phase 1: phi_s. Each warp computes 32 a's, 2 at a time (ILP).
    #pragma unroll 1
    for (int i = 0; i < 32; i += 2) {
        const int a0 = warp * 32 + i;
        const int a1 = a0 + 1;
        const float4* w0 = (const float4*)(phi_w + (size_t)a0 * DD);
        const float4* w1 = (const float4*)(phi_w + (size_t)a1 * DD);
        float acc0 = 0.f, acc1 = 0.f;
        #pragma unroll
        for (int j = 0; j < 4; j++) {
            float4 sv = s4[lane + 32 * j];
            float4 wa = w0[lane + 32 * j];
            float4 wb = w1[lane + 32 * j];
            acc0 += wa.x * sv.x + wa.y * sv.y + wa.z * sv.z + wa.w * sv.w;
            acc1 += wb.x * sv.x + wb.y * sv.y + wb.z * sv.z + wb.w * sv.w;
        }
        #pragma unroll
        for (int off = 16; off; off >>= 1) {
            acc0 += __shfl_xor_sync(0xffffffffu, acc0, off);
            acc1 += __shfl_xor_sync(0xffffffffu, acc1, off);
        }
        if (lane == 0) {
            sh_ph[a0] = acc0 + phi_b[a0];
            sh_ph[a1] = acc1 + phi_b[a1];
        }
    }
    __syncthreads();

    // Phase 2: v[b,k]. 4 groups of 128 threads; group g covers a in
    // [128g, 128g+128); thread kk owns columns [4kk, 4kk+4) (float4).
    const int group = tid >> 7;            // 0..3
    const int kk    = tid & 127;
    const float4* pw4 = (const float4*)psi_w;   // [a][128] float4
    float4 acc = make_float4(0.f, 0.f, 0.f, 0.f);
    const int abase = group * 128;
    #pragma unroll 4
    for (int a = abase; a < abase + 128; a++) {
        const float  p = sh_ph[a];                       // LDS broadcast
        const float4 w = pw4[(size_t)a * 128 + kk];      // coalesced 128B
        acc.x += p * w.x; acc.y += p * w.y;
        acc.z += p * w.z; acc.w += p * w.w;
    }
    sh_vp[group][kk] = acc;
    __syncthreads();

    if (tid < 128) {
        float4 r0 = sh_vp[0][tid], r1 = sh_vp[1][tid];
        float4 r2 = sh_vp[2][tid], r3 = sh_vp[3][tid];
        float4 o;
        o.x = (r0.x + r1.x) + (r2.x + r3.x);
        o.y = (r0.y + r1.y) + (r2.y + r3.y);
        o.z = (r0.z + r1.z) + (r2.z + r3.z);
        o.w = (r0.w + r1.w) + (r2.w + r3.w);
        ((float4*)(g_v + (size_t)b * DD))[tid] = o;
    }
}

// ---------------------------------------------------------------------------
// k_scores: THE DRAM-bound pass. One streaming read of h (268 MB) produces
// e[b,t] = v[b].h[b,t] and hsum[b,t] = sum_k h[b,t,k].
// Each warp: v held in 16 registers (loaded ONCE), 4 rows processed with
// 2-row unroll -> 8 independent LDG.128 in flight per lane.
// grid 4096 x block 256: 8 warps x 4 rows = 32 rows/block, 131072 rows total.
// 2048 % 32 == 0 so a block never straddles a b boundary.
// ---------------------------------------------------------------------------
__global__ void k_scores(const float* __restrict__ h) {
    const int lane = threadIdx.x & 31;
    const int warp = threadIdx.x >> 5;
    const int row0 = blockIdx.x * 32 + warp * 4;
    const int b    = row0 >> 11;           // row / 2048

    const float4* v4 = (const float4*)(g_v + (size_t)b * DD);
    float4 v[4];
    #pragma unroll
    for (int j = 0; j < 4; j++) v[j] = v4[lane + 32 * j];

    #pragma unroll
    for (int r = 0; r < 4; r += 2) {
        const float4* ha = (const float4*)(h + (size_t)(row0 + r)     * DD);
        const float4* hb = (const float4*)(h + (size_t)(row0 + r + 1) * DD);
        float4 A[4], B[4];
        #pragma unroll
        for (int j = 0; j < 4; j++) A[j] = ha[lane + 32 * j];
        #pragma unroll
        for (int j = 0; j < 4; j++) B[j] = hb[lane + 32 * j];

        float e0 = 0.f, s0 = 0.f, e1 = 0.f, s1 = 0.f;
        #pragma unroll
        for (int j = 0; j < 4; j++) {
            e0 += A[j].x * v[j].x + A[j].y * v[j].y + A[j].z * v[j].z + A[j].w * v[j].w;
            s0 += (A[j].x + A[j].y) + (A[j].z + A[j].w);
            e1 += B[j].x * v[j].x + B[j].y * v[j].y + B[j].z * v[j].z + B[j].w * v[j].w;
            s1 += (B[j].x + B[j].y) + (B[j].z + B[j].w);
        }
        #pragma unroll
        for (int off = 16; off; off >>= 1) {
            e0 += __shfl_xor_sync(0xffffffffu, e0, off);
            s0 += __shfl_xor_sync(0xffffffffu, s0, off);
            e1 += __shfl_xor_sync(0xffffffffu, e1, off);
            s1 += __shfl_xor_sync(0xffffffffu, s1, off);
        }
        if (lane == 0) {
            g_e[row0 + r]        = e0;
            g_hsum[row0 + r]     = s0;
            g_e[row0 + r + 1]    = e1;
            g_hsum[row0 + r + 1] = s1;
        }
    }
}

// ---------------------------------------------------------------------------
// k_softmax: per-b softmax over T=2048 + output c = alpha * hsum.
// 64 blocks x 512 threads, float4 everywhere, __expf, one smem reduce array.
// ---------------------------------------------------------------------------
__global__ void k_softmax(float* __restrict__ out) {
    const int b    = blockIdx.x;
    const int tid  = threadIdx.x;          // 512 -> 4 elems/thread
    const int lane = tid & 31;
    const int warp = tid >> 5;             // 16 warps
    __shared__ float red[16];

    const float4 e = ((const float4*)(g_e + (size_t)b * TT))[tid];

    float m = fmaxf(fmaxf(e.x, e.y), fmaxf(e.z, e.w));
    #pragma unroll
    for (int off = 16; off; off >>= 1)
        m = fmaxf(m, __shfl_xor_sync(0xffffffffu, m, off));
    if (lane == 0) red[warp] = m;
    __syncthreads();
    float M = red[0];
    #pragma unroll
    for (int w = 1; w < 16; w++) M = fmaxf(M, red[w]);
    __syncthreads();

    float4 ex;
    ex.x = __expf(e.x - M); ex.y = __expf(e.y - M);
    ex.z = __expf(e.z - M); ex.w = __expf(e.w - M);
    float sum = (ex.x + ex.y) + (ex.z + ex.w);
    #pragma unroll
    for (int off = 16; off; off >>= 1)
        sum += __shfl_xor_sync(0xffffffffu, sum, off);
    if (lane == 0) red[warp] = sum;
    __syncthreads();
    float S = 0.f;
    #pragma unroll
    for (int w = 0; w < 16; w++) S += red[w];
    const float inv = 1.f / S;

    const float4 hs = ((const float4*)(g_hsum + (size_t)b * TT))[tid];
    float4 o;
    o.x = ex.x * inv * hs.x; o.y = ex.y * inv * hs.y;
    o.z = ex.z * inv * hs.z; o.w = ex.w * inv * hs.w;
    ((float4*)(out + (size_t)b * TT))[tid] = o;
}

// ---------------------------------------------------------------------------
extern "C" void kernel_launch(void* const* d_in, const int* in_sizes, int n_in,
                              void* d_out, int out_size) {
    const float* s     = (const float*)d_in[0];   // [64, 512]
    const float* h     = (const float*)d_in[1];   // [64, 2048, 512]
    const float* phi_w = (const float*)d_in[2];   // [512, 512]
    const float* phi_b = (const float*)d_in[3];   // [512]
    const float* psi_w = (const float*)d_in[4];   // [512, 512]
    // d_in[5] = psi_b: unused (softmax shift invariance)
    float* out = (float*)d_out;                   // [64, 2048] fp32

    k_prep<<<64, 512>>>(s, phi_w, phi_b, psi_w);
    k_scores<<<4096, 256>>>(h);     // 4096 * 32 rows = 131072 = BB*TT
    k_softmax<<<64, 512>>>(out);
}

// round 4
// speedup vs baseline: 1.8210x; 1.3951x over previous
#include <cuda_runtime.h>

#define BB 64
#define TT 2048
#define DD 512

// Scratch (allocation-free contract: __device__ globals)
__device__ float g_phis[BB * DD];
__device__ float g_v[BB * DD];
__device__ float g_e[BB * TT];
__device__ float g_hsum[BB * TT];

// ---------------------------------------------------------------------------
// k_phis: phi_s[b,a] = dot(s[b,:], phi_w[a,:]) + phi_b[a]
// grid (32 a-tiles, 64 b) = 2048 blocks x 256 threads. Each warp does 2 a's.
// ~14 blocks/SM -> latency fully hidden; phi_w is L2-hot after first wave.
// ---------------------------------------------------------------------------
__global__ void k_phis(const float* __restrict__ s,
                       const float* __restrict__ phi_w,
                       const float* __restrict__ phi_b) {
    const int b    = blockIdx.y;
    const int tid  = threadIdx.x;          // 256
    const int lane = tid & 31;
    const int warp = tid >> 5;             // 8 warps

    __shared__ float sh_s[DD];
    sh_s[tid]       = s[(size_t)b * DD + tid];
    sh_s[tid + 256] = s[(size_t)b * DD + tid + 256];
    __syncthreads();
    const float4* s4 = (const float4*)sh_s;

    const int a0 = blockIdx.x * 16 + warp * 2;
    const int a1 = a0 + 1;
    const float4* w0 = (const float4*)(phi_w + (size_t)a0 * DD);
    const float4* w1 = (const float4*)(phi_w + (size_t)a1 * DD);

    float acc0 = 0.f, acc1 = 0.f;
    #pragma unroll
    for (int j = 0; j < 4; j++) {
        float4 wa = w0[lane + 32 * j];
        float4 wb = w1[lane + 32 * j];
        float4 sv = s4[lane + 32 * j];
        acc0 += wa.x * sv.x + wa.y * sv.y + wa.z * sv.z + wa.w * sv.w;
        acc1 += wb.x * sv.x + wb.y * sv.y + wb.z * sv.z + wb.w * sv.w;
    }
    #pragma unroll
    for (int off = 16; off; off >>= 1) {
        acc0 += __shfl_xor_sync(0xffffffffu, acc0, off);
        acc1 += __shfl_xor_sync(0xffffffffu, acc1, off);
    }
    if (lane == 0) {
        g_phis[b * DD + a0] = acc0 + phi_b[a0];
        g_phis[b * DD + a1] = acc1 + phi_b[a1];
    }
}

// ---------------------------------------------------------------------------
// k_v: v[b,k] = sum_a phi_s[b,a] * psi_w[a,k]
// grid (32 b-pairs, 4 k-slices) = 128 blocks x 512 threads (16 warps).
// Warp w covers a in [32w, 32w+32); lane owns one float4 column of the
// 128-float k-slice. Two b's per block halve psi_w L2 traffic (32 MB total).
// psi_b dropped: softmax is shift-invariant to the per-b constant it adds.
// ---------------------------------------------------------------------------
__global__ void k_v(const float* __restrict__ psi_w) {
    const int b0   = blockIdx.x * 2;
    const int ks   = blockIdx.y;           // k-slice: 32 float4 columns
    const int tid  = threadIdx.x;          // 512
    const int lane = tid & 31;
    const int warp = tid >> 5;             // 16 warps

    __shared__ float  ph0[DD], ph1[DD];
    __shared__ float4 part0[16][32];
    __shared__ float4 part1[16][32];

    ph0[tid] = g_phis[(size_t)b0 * DD + tid];
    ph1[tid] = g_phis[(size_t)(b0 + 1) * DD + tid];
    __syncthreads();

    const float4* w4 = (const float4*)psi_w;     // [512][128] float4
    const int col = ks * 32 + lane;              // 0..127

    float4 acc0 = make_float4(0.f, 0.f, 0.f, 0.f);
    float4 acc1 = make_float4(0.f, 0.f, 0.f, 0.f);
    const int abase = warp * 32;
    #pragma unroll 8
    for (int i = 0; i < 32; i++) {
        const int a = abase + i;
        const float4 w = w4[(size_t)a * 128 + col];
        const float p0 = ph0[a], p1 = ph1[a];
        acc0.x += p0 * w.x; acc0.y += p0 * w.y;
        acc0.z += p0 * w.z; acc0.w += p0 * w.w;
        acc1.x += p1 * w.x; acc1.y += p1 * w.y;
        acc1.z += p1 * w.z; acc1.w += p1 * w.w;
    }
    part0[warp][lane] = acc0;
    part1[warp][lane] = acc1;
    __syncthreads();

    if (warp == 0) {
        float4 r = part0[0][lane];
        #pragma unroll
        for (int w = 1; w < 16; w++) {
            float4 p = part0[w][lane];
            r.x += p.x; r.y += p.y; r.z += p.z; r.w += p.w;
        }
        ((float4*)g_v)[(size_t)b0 * 128 + col] = r;
    } else if (warp == 1) {
        float4 r = part1[0][lane];
        #pragma unroll
        for (int w = 1; w < 16; w++) {
            float4 p = part1[w][lane];
            r.x += p.x; r.y += p.y; r.z += p.z; r.w += p.w;
        }
        ((float4*)g_v)[(size_t)(b0 + 1) * 128 + col] = r;
    }
}

// ---------------------------------------------------------------------------
// k_scores: THE DRAM-bound pass. One streaming read of h (268 MB) produces
// e[b,t] = v[b].h[b,t] and hsum[b,t] = sum_k h[b,t,k].
// Warp: v pinned in 16 regs; 4 rows per warp, ALL 16 LDG.128 issued before
// any compute (MLP=16/lane). Lane 0 writes 4-row results as float4.
// grid 4096 x block 256 (8 warps x 4 rows = 32 rows/block; 2048%32==0 so
// blocks never straddle a b boundary).
// ---------------------------------------------------------------------------
__global__ void __launch_bounds__(256, 2) k_scores(const float* __restrict__ h) {
    const int lane = threadIdx.x & 31;
    const int warp = threadIdx.x >> 5;
    const int row0 = blockIdx.x * 32 + warp * 4;
    const int b    = row0 >> 11;           // row / 2048

    const float4* v4 = (const float4*)(g_v + (size_t)b * DD);
    float4 v[4];
    #pragma unroll
    for (int j = 0; j < 4; j++) v[j] = v4[lane + 32 * j];

    const float4* hp = (const float4*)(h + (size_t)row0 * DD);
    float4 A[4][4];
    #pragma unroll
    for (int r = 0; r < 4; r++)
        #pragma unroll
        for (int j = 0; j < 4; j++)
            A[r][j] = hp[r * 128 + lane + 32 * j];

    float e[4], hs[4];
    #pragma unroll
    for (int r = 0; r < 4; r++) {
        float ee = 0.f, ss = 0.f;
        #pragma unroll
        for (int j = 0; j < 4; j++) {
            ee += A[r][j].x * v[j].x + A[r][j].y * v[j].y
                + A[r][j].z * v[j].z + A[r][j].w * v[j].w;
            ss += (A[r][j].x + A[r][j].y) + (A[r][j].z + A[r][j].w);
        }
        e[r] = ee; hs[r] = ss;
    }
    #pragma unroll
    for (int off = 16; off; off >>= 1) {
        #pragma unroll
        for (int r = 0; r < 4; r++) {
            e[r]  += __shfl_xor_sync(0xffffffffu, e[r],  off);
            hs[r] += __shfl_xor_sync(0xffffffffu, hs[r], off);
        }
    }
    if (lane == 0) {
        *(float4*)(g_e    + row0) = make_float4(e[0],  e[1],  e[2],  e[3]);
        *(float4*)(g_hsum + row0) = make_float4(hs[0], hs[1], hs[2], hs[3]);
    }
}

// ---------------------------------------------------------------------------
// k_softmax: per-b softmax over T=2048 + output c = alpha * hsum.
// 64 blocks x 512 threads, float4 everywhere, __expf, one smem reduce array.
// ---------------------------------------------------------------------------
__global__ void k_softmax(float* __restrict__ out) {
    const int b    = blockIdx.x;
    const int tid  = threadIdx.x;          // 512 -> 4 elems/thread
    const int lane = tid & 31;
    const int warp = tid >> 5;             // 16 warps
    __shared__ float red[16];

    const float4 e = ((const float4*)(g_e + (size_t)b * TT))[tid];

    float m = fmaxf(fmaxf(e.x, e.y), fmaxf(e.z, e.w));
    #pragma unroll
    for (int off = 16; off; off >>= 1)
        m = fmaxf(m, __shfl_xor_sync(0xffffffffu, m, off));
    if (lane == 0) red[warp] = m;
    __syncthreads();
    float M = red[0];
    #pragma unroll
    for (int w = 1; w < 16; w++) M = fmaxf(M, red[w]);
    __syncthreads();

    float4 ex;
    ex.x = __expf(e.x - M); ex.y = __expf(e.y - M);
    ex.z = __expf(e.z - M); ex.w = __expf(e.w - M);
    float sum = (ex.x + ex.y) + (ex.z + ex.w);
    #pragma unroll
    for (int off = 16; off; off >>= 1)
        sum += __shfl_xor_sync(0xffffffffu, sum, off);
    if (lane == 0) red[warp] = sum;
    __syncthreads();
    float S = 0.f;
    #pragma unroll
    for (int w = 0; w < 16; w++) S += red[w];
    const float inv = 1.f / S;

    const float4 hs = ((const float4*)(g_hsum + (size_t)b * TT))[tid];
    float4 o;
    o.x = ex.x * inv * hs.x; o.y = ex.y * inv * hs.y;
    o.z = ex.z * inv * hs.z; o.w = ex.w * inv * hs.w;
    ((float4*)(out + (size_t)b * TT))[tid] = o;
}

// ---------------------------------------------------------------------------
extern "C" void kernel_launch(void* const* d_in, const int* in_sizes, int n_in,
                              void* d_out, int out_size) {
    const float* s     = (const float*)d_in[0];   // [64, 512]
    const float* h     = (const float*)d_in[1];   // [64, 2048, 512]
    const float* phi_w = (const float*)d_in[2];   // [512, 512]
    const float* phi_b = (const float*)d_in[3];   // [512]
    const float* psi_w = (const float*)d_in[4];   // [512, 512]
    // d_in[5] = psi_b: unused (softmax shift invariance)
    float* out = (float*)d_out;                   // [64, 2048] fp32

    k_phis<<<dim3(32, 64), 256>>>(s, phi_w, phi_b);
    k_v<<<dim3(32, 4), 512>>>(psi_w);
    k_scores<<<4096, 256>>>(h);
    k_softmax<<<64, 512>>>(out);
}